// round 1
// baseline (speedup 1.0000x reference)
#include <cuda_runtime.h>
#include <math.h>

typedef unsigned long long ull;

#define Bn   192
#define Sn   512
#define En   128
#define Nrows (Bn * Sn)
#define SP   130   // smem row pitch (floats): even (8B-aligned float2) and 130%32==2 -> conflict-free strided LDS.64

// -------- scratch (device globals; no allocations allowed) --------
__device__ float g_q [Nrows * En];
__device__ float g_k [Nrows * En];
__device__ float g_v [Nrows * En];
__device__ float g_ao[Nrows * En];

// -------- packed f32x2 helpers (Blackwell: 2x fp32 FMA throughput) --------
__device__ __forceinline__ ull ffma2(ull a, ull b, ull c) {
    ull d;
    asm("fma.rn.f32x2 %0, %1, %2, %3;" : "=l"(d) : "l"(a), "l"(b), "l"(c));
    return d;
}
__device__ __forceinline__ ull pk2(float lo, float hi) {
    ull r;
    asm("mov.b64 %0, {%1, %2};" : "=l"(r) : "f"(lo), "f"(hi));
    return r;
}
__device__ __forceinline__ float2 upk2(ull v) {
    float2 f;
    asm("mov.b64 {%0, %1}, %2;" : "=f"(f.x), "=f"(f.y) : "l"(v));
    return f;
}

// =====================================================================
// Kernel 1: fused LayerNorm + ReLU + QKV projection
// block: 256 threads, 64 rows. smem: xs[64][SP] + W[128][SP]
// =====================================================================
#define QKV_SMEM_BYTES ((64 * SP + 128 * SP) * 4)

__global__ __launch_bounds__(256, 2) void qkv_kernel(
    const float* __restrict__ x,
    const float* __restrict__ Wq, const float* __restrict__ bq,
    const float* __restrict__ Wk, const float* __restrict__ bk,
    const float* __restrict__ Wv, const float* __restrict__ bv)
{
    extern __shared__ float sm[];
    float* xs = sm;              // 64 * SP
    float* Ws = sm + 64 * SP;    // 128 * SP

    const int tid  = threadIdx.x;
    const int r0   = blockIdx.x * 64;
    const int w    = tid >> 5;
    const int lane = tid & 31;

    // ---- LayerNorm + ReLU into smem (warp w handles rows w*8 .. w*8+7) ----
    #pragma unroll
    for (int r = 0; r < 8; ++r) {
        const int row = w * 8 + r;
        float4 v = ((const float4*)(x + (size_t)(r0 + row) * En))[lane];
        float s = v.x + v.y + v.z + v.w;
        #pragma unroll
        for (int o = 16; o; o >>= 1) s += __shfl_xor_sync(0xffffffffu, s, o);
        const float mean = s * (1.0f / En);
        const float a0 = v.x - mean, a1 = v.y - mean, a2 = v.z - mean, a3 = v.w - mean;
        float q = a0 * a0 + a1 * a1 + a2 * a2 + a3 * a3;
        #pragma unroll
        for (int o = 16; o; o >>= 1) q += __shfl_xor_sync(0xffffffffu, q, o);
        const float rs = rsqrtf(q * (1.0f / En) + 1e-5f);
        float* d = &xs[row * SP + lane * 4];
        d[0] = fmaxf(a0 * rs, 0.0f);
        d[1] = fmaxf(a1 * rs, 0.0f);
        d[2] = fmaxf(a2 * rs, 0.0f);
        d[3] = fmaxf(a3 * rs, 0.0f);
    }

    const float* Wl[3] = {Wq, Wk, Wv};
    const float* bl[3] = {bq, bk, bv};
    float*       Ol[3] = {g_q, g_k, g_v};

    const int tx = tid & 31;   // output-column lane
    const int ty = tid >> 5;   // row-group (8 rows)

    #pragma unroll
    for (int m = 0; m < 3; ++m) {
        __syncthreads();   // xs ready (m=0) / previous GEMM done reading Ws (m>0)
        const float* W = Wl[m];
        for (int i = tid; i < 128 * 32; i += 256) {
            float4 t = ((const float4*)W)[i];
            const int c = i >> 5, e = (i & 31) << 2;
            float* d = &Ws[c * SP + e];
            d[0] = t.x; d[1] = t.y; d[2] = t.z; d[3] = t.w;
        }
        __syncthreads();

        ull acc[8][4];
        #pragma unroll
        for (int r = 0; r < 8; ++r)
            #pragma unroll
            for (int c = 0; c < 4; ++c) acc[r][c] = 0ull;

        #pragma unroll 8
        for (int e2 = 0; e2 < 64; ++e2) {
            ull wv[4];
            #pragma unroll
            for (int c = 0; c < 4; ++c)
                wv[c] = *(const ull*)&Ws[(tx + 32 * c) * SP + 2 * e2];
            #pragma unroll
            for (int r = 0; r < 8; ++r) {
                const ull xv = *(const ull*)&xs[(ty * 8 + r) * SP + 2 * e2];
                #pragma unroll
                for (int c = 0; c < 4; ++c) acc[r][c] = ffma2(xv, wv[c], acc[r][c]);
            }
        }

        float* O = Ol[m];
        #pragma unroll
        for (int c = 0; c < 4; ++c) {
            const float bb = bl[m][tx + 32 * c];
            #pragma unroll
            for (int r = 0; r < 8; ++r) {
                const float2 f = upk2(acc[r][c]);
                O[(size_t)(r0 + ty * 8 + r) * En + tx + 32 * c] = f.x + f.y + bb;
            }
        }
    }
}

// =====================================================================
// Kernel 2: masked attention. block = (batch b, 64-query tile)
// smem: Qs[64][SP] + KVs[64][SP] + L[64][512] + deg[64] + isum[64]
// =====================================================================
#define ATTN_SMEM_BYTES ((64 * SP * 2 + 64 * 512 + 128) * 4)

__device__ __forceinline__ void load_tile64(float* dst, const float* __restrict__ src) {
    for (int i = threadIdx.x; i < 64 * 32; i += 256) {
        float4 t = ((const float4*)src)[i];
        const int r = i >> 5, e = (i & 31) << 2;
        float* d = &dst[r * SP + e];
        d[0] = t.x; d[1] = t.y; d[2] = t.z; d[3] = t.w;
    }
}

__global__ __launch_bounds__(256) void attn_kernel(const float* __restrict__ adj)
{
    extern __shared__ float sm[];
    float* Qs   = sm;                    // 64*SP
    float* KVs  = Qs + 64 * SP;          // 64*SP
    float* L    = KVs + 64 * SP;         // 64*512
    float* deg  = L + 64 * 512;          // 64
    float* isum = deg + 64;              // 64

    const int b   = blockIdx.y;
    const int q0  = blockIdx.x * 64;
    const int tid = threadIdx.x;

    if (tid < 64) deg[tid] = 0.0f;
    load_tile64(Qs, g_q + ((size_t)b * Sn + q0) * En);
    __syncthreads();

    const int tx = tid & 15;   // key lane
    const int ty = tid >> 4;   // query lane (16)

    float degacc[4] = {0.f, 0.f, 0.f, 0.f};

    // ---- pass 1: logits = mask(Q K^T), fused adj read + degree ----
    for (int kt = 0; kt < 8; ++kt) {
        load_tile64(KVs, g_k + ((size_t)b * Sn + kt * 64) * En);
        __syncthreads();

        ull acc[4][4];
        #pragma unroll
        for (int qi = 0; qi < 4; ++qi)
            #pragma unroll
            for (int ki = 0; ki < 4; ++ki) acc[qi][ki] = 0ull;

        #pragma unroll 8
        for (int e2 = 0; e2 < 64; ++e2) {
            ull kvv[4], qvv[4];
            #pragma unroll
            for (int ki = 0; ki < 4; ++ki)
                kvv[ki] = *(const ull*)&KVs[(tx + 16 * ki) * SP + 2 * e2];
            #pragma unroll
            for (int qi = 0; qi < 4; ++qi)
                qvv[qi] = *(const ull*)&Qs[(ty + 16 * qi) * SP + 2 * e2];
            #pragma unroll
            for (int qi = 0; qi < 4; ++qi)
                #pragma unroll
                for (int ki = 0; ki < 4; ++ki)
                    acc[qi][ki] = ffma2(qvv[qi], kvv[ki], acc[qi][ki]);
        }

        #pragma unroll
        for (int qi = 0; qi < 4; ++qi) {
            const int q = ty + 16 * qi;
            const float* arow = adj + ((size_t)b * Sn + q0 + q) * Sn + kt * 64;
            #pragma unroll
            for (int ki = 0; ki < 4; ++ki) {
                const int k = tx + 16 * ki;
                const float a = arow[k];
                degacc[qi] += a;
                const float2 f = upk2(acc[qi][ki]);
                L[q * 512 + kt * 64 + k] = (a != 0.0f) ? (f.x + f.y) : -INFINITY;
            }
        }
        __syncthreads();
    }

    #pragma unroll
    for (int qi = 0; qi < 4; ++qi) atomicAdd(&deg[ty + 16 * qi], degacc[qi]);
    __syncthreads();

    // ---- softmax over 512 keys; warp handles 8 queries ----
    {
        const int w = tid >> 5, lane = tid & 31;
        for (int j = 0; j < 8; ++j) {
            const int q = w * 8 + j;
            const float s = rsqrtf(deg[q]);
            float m = -INFINITY;
            for (int kk = lane; kk < 512; kk += 32)
                m = fmaxf(m, L[q * 512 + kk] * s);
            #pragma unroll
            for (int o = 16; o; o >>= 1) m = fmaxf(m, __shfl_xor_sync(0xffffffffu, m, o));
            float sum = 0.0f;
            for (int kk = lane; kk < 512; kk += 32) {
                const float p = __expf(L[q * 512 + kk] * s - m);
                L[q * 512 + kk] = p;
                sum += p;
            }
            #pragma unroll
            for (int o = 16; o; o >>= 1) sum += __shfl_xor_sync(0xffffffffu, sum, o);
            if (lane == 0) isum[q] = 1.0f / sum;
        }
    }
    __syncthreads();

    // ---- pass 2: out = P V ----
    ull oacc[4][4];   // 4 queries x 4 float2 output slots (8 cols)
    #pragma unroll
    for (int qi = 0; qi < 4; ++qi)
        #pragma unroll
        for (int ei = 0; ei < 4; ++ei) oacc[qi][ei] = 0ull;

    for (int kt = 0; kt < 8; ++kt) {
        load_tile64(KVs, g_v + ((size_t)b * Sn + kt * 64) * En);
        __syncthreads();

        #pragma unroll 4
        for (int k = 0; k < 64; ++k) {
            ull vv[4];
            #pragma unroll
            for (int ei = 0; ei < 4; ++ei)
                vv[ei] = *(const ull*)&KVs[k * SP + 2 * (tx + 16 * ei)];
            #pragma unroll
            for (int qi = 0; qi < 4; ++qi) {
                const float p = L[(ty + 16 * qi) * 512 + kt * 64 + k];
                const ull p2 = pk2(p, p);
                #pragma unroll
                for (int ei = 0; ei < 4; ++ei)
                    oacc[qi][ei] = ffma2(p2, vv[ei], oacc[qi][ei]);
            }
        }
        __syncthreads();
    }

    float* Og = g_ao + ((size_t)b * Sn + q0) * En;
    #pragma unroll
    for (int qi = 0; qi < 4; ++qi) {
        const int q = ty + 16 * qi;
        const float is = isum[q];
        #pragma unroll
        for (int ei = 0; ei < 4; ++ei) {
            const float2 f = upk2(oacc[qi][ei]);
            *(float2*)&Og[q * En + 2 * (tx + 16 * ei)] = make_float2(f.x * is, f.y * is);
        }
    }
}

// =====================================================================
// Kernel 3: LN + ReLU + output projection + residual
// =====================================================================
__global__ __launch_bounds__(256, 2) void out_kernel(
    const float* __restrict__ x,
    const float* __restrict__ Wo, const float* __restrict__ bo,
    float* __restrict__ out)
{
    extern __shared__ float sm[];
    float* xs = sm;
    float* Ws = sm + 64 * SP;

    const int tid  = threadIdx.x;
    const int r0   = blockIdx.x * 64;
    const int w    = tid >> 5;
    const int lane = tid & 31;

    #pragma unroll
    for (int r = 0; r < 8; ++r) {
        const int row = w * 8 + r;
        float4 v = ((const float4*)(g_ao + (size_t)(r0 + row) * En))[lane];
        float s = v.x + v.y + v.z + v.w;
        #pragma unroll
        for (int o = 16; o; o >>= 1) s += __shfl_xor_sync(0xffffffffu, s, o);
        const float mean = s * (1.0f / En);
        const float a0 = v.x - mean, a1 = v.y - mean, a2 = v.z - mean, a3 = v.w - mean;
        float q = a0 * a0 + a1 * a1 + a2 * a2 + a3 * a3;
        #pragma unroll
        for (int o = 16; o; o >>= 1) q += __shfl_xor_sync(0xffffffffu, q, o);
        const float rs = rsqrtf(q * (1.0f / En) + 1e-5f);
        float* d = &xs[row * SP + lane * 4];
        d[0] = fmaxf(a0 * rs, 0.0f);
        d[1] = fmaxf(a1 * rs, 0.0f);
        d[2] = fmaxf(a2 * rs, 0.0f);
        d[3] = fmaxf(a3 * rs, 0.0f);
    }
    __syncthreads();

    for (int i = tid; i < 128 * 32; i += 256) {
        float4 t = ((const float4*)Wo)[i];
        const int c = i >> 5, e = (i & 31) << 2;
        float* d = &Ws[c * SP + e];
        d[0] = t.x; d[1] = t.y; d[2] = t.z; d[3] = t.w;
    }
    __syncthreads();

    const int tx = tid & 31;
    const int ty = tid >> 5;

    ull acc[8][4];
    #pragma unroll
    for (int r = 0; r < 8; ++r)
        #pragma unroll
        for (int c = 0; c < 4; ++c) acc[r][c] = 0ull;

    #pragma unroll 8
    for (int e2 = 0; e2 < 64; ++e2) {
        ull wv[4];
        #pragma unroll
        for (int c = 0; c < 4; ++c)
            wv[c] = *(const ull*)&Ws[(tx + 32 * c) * SP + 2 * e2];
        #pragma unroll
        for (int r = 0; r < 8; ++r) {
            const ull xv = *(const ull*)&xs[(ty * 8 + r) * SP + 2 * e2];
            #pragma unroll
            for (int c = 0; c < 4; ++c) acc[r][c] = ffma2(xv, wv[c], acc[r][c]);
        }
    }

    #pragma unroll
    for (int c = 0; c < 4; ++c) {
        const float bb = bo[tx + 32 * c];
        #pragma unroll
        for (int r = 0; r < 8; ++r) {
            const size_t idx = (size_t)(r0 + ty * 8 + r) * En + tx + 32 * c;
            const float2 f = upk2(acc[r][c]);
            out[idx] = x[idx] + f.x + f.y + bb;
        }
    }
}

// =====================================================================
extern "C" void kernel_launch(void* const* d_in, const int* in_sizes, int n_in,
                              void* d_out, int out_size) {
    const float* x   = (const float*)d_in[0];
    const float* adj = (const float*)d_in[1];
    const float* Wq  = (const float*)d_in[2];
    const float* bq  = (const float*)d_in[3];
    const float* Wk  = (const float*)d_in[4];
    const float* bk  = (const float*)d_in[5];
    const float* Wv  = (const float*)d_in[6];
    const float* bv  = (const float*)d_in[7];
    const float* Wo  = (const float*)d_in[8];
    const float* bo  = (const float*)d_in[9];
    float* out = (float*)d_out;

    cudaFuncSetAttribute(qkv_kernel,  cudaFuncAttributeMaxDynamicSharedMemorySize, QKV_SMEM_BYTES);
    cudaFuncSetAttribute(attn_kernel, cudaFuncAttributeMaxDynamicSharedMemorySize, ATTN_SMEM_BYTES);
    cudaFuncSetAttribute(out_kernel,  cudaFuncAttributeMaxDynamicSharedMemorySize, QKV_SMEM_BYTES);

    qkv_kernel<<<Nrows / 64, 256, QKV_SMEM_BYTES>>>(x, Wq, bq, Wk, bk, Wv, bv);
    attn_kernel<<<dim3(Sn / 64, Bn), 256, ATTN_SMEM_BYTES>>>(adj);
    out_kernel<<<Nrows / 64, 256, QKV_SMEM_BYTES>>>(x, Wo, bo, out);
}

// round 2
// speedup vs baseline: 1.0073x; 1.0073x over previous
#include <cuda_runtime.h>
#include <math.h>

typedef unsigned long long ull;

#define Bn   192
#define Sn   512
#define En   128
#define Nrows (Bn * Sn)
#define SP   130   // smem row pitch (floats): even (8B-aligned float2) and 130%32==2 -> conflict-free strided LDS.64

// -------- scratch (device globals; no allocations allowed) --------
__device__ float g_q [Nrows * En];
__device__ float g_k [Nrows * En];
__device__ float g_v [Nrows * En];
__device__ float g_ao[Nrows * En];

// -------- packed f32x2 helpers (Blackwell: 2x fp32 FMA throughput) --------
__device__ __forceinline__ ull ffma2(ull a, ull b, ull c) {
    ull d;
    asm("fma.rn.f32x2 %0, %1, %2, %3;" : "=l"(d) : "l"(a), "l"(b), "l"(c));
    return d;
}
__device__ __forceinline__ ull pk2(float lo, float hi) {
    ull r;
    asm("mov.b64 %0, {%1, %2};" : "=l"(r) : "f"(lo), "f"(hi));
    return r;
}
__device__ __forceinline__ float2 upk2(ull v) {
    float2 f;
    asm("mov.b64 {%0, %1}, %2;" : "=f"(f.x), "=f"(f.y) : "l"(v));
    return f;
}

// =====================================================================
// Kernel 1: fused LayerNorm + ReLU + QKV projection
// block: 256 threads, 64 rows. smem: xs[64][SP] + W[128][SP]
// =====================================================================
#define QKV_SMEM_BYTES ((64 * SP + 128 * SP) * 4)

__global__ __launch_bounds__(256, 2) void qkv_kernel(
    const float* __restrict__ x,
    const float* __restrict__ Wq, const float* __restrict__ bq,
    const float* __restrict__ Wk, const float* __restrict__ bk,
    const float* __restrict__ Wv, const float* __restrict__ bv)
{
    extern __shared__ float sm[];
    float* xs = sm;              // 64 * SP
    float* Ws = sm + 64 * SP;    // 128 * SP

    const int tid  = threadIdx.x;
    const int r0   = blockIdx.x * 64;
    const int w    = tid >> 5;
    const int lane = tid & 31;

    // ---- LayerNorm + ReLU into smem (warp w handles rows w*8 .. w*8+7) ----
    #pragma unroll
    for (int r = 0; r < 8; ++r) {
        const int row = w * 8 + r;
        float4 v = ((const float4*)(x + (size_t)(r0 + row) * En))[lane];
        float s = v.x + v.y + v.z + v.w;
        #pragma unroll
        for (int o = 16; o; o >>= 1) s += __shfl_xor_sync(0xffffffffu, s, o);
        const float mean = s * (1.0f / En);
        const float a0 = v.x - mean, a1 = v.y - mean, a2 = v.z - mean, a3 = v.w - mean;
        float q = a0 * a0 + a1 * a1 + a2 * a2 + a3 * a3;
        #pragma unroll
        for (int o = 16; o; o >>= 1) q += __shfl_xor_sync(0xffffffffu, q, o);
        const float rs = rsqrtf(q * (1.0f / En) + 1e-5f);
        float* d = &xs[row * SP + lane * 4];
        d[0] = fmaxf(a0 * rs, 0.0f);
        d[1] = fmaxf(a1 * rs, 0.0f);
        d[2] = fmaxf(a2 * rs, 0.0f);
        d[3] = fmaxf(a3 * rs, 0.0f);
    }

    const float* Wl[3] = {Wq, Wk, Wv};
    const float* bl[3] = {bq, bk, bv};
    float*       Ol[3] = {g_q, g_k, g_v};

    const int tx = tid & 31;   // output-column lane
    const int ty = tid >> 5;   // row-group (8 rows)

    #pragma unroll
    for (int m = 0; m < 3; ++m) {
        __syncthreads();   // xs ready (m=0) / previous GEMM done reading Ws (m>0)
        const float* W = Wl[m];
        for (int i = tid; i < 128 * 32; i += 256) {
            float4 t = ((const float4*)W)[i];
            const int c = i >> 5, e = (i & 31) << 2;
            float* d = &Ws[c * SP + e];
            d[0] = t.x; d[1] = t.y; d[2] = t.z; d[3] = t.w;
        }
        __syncthreads();

        ull acc[8][4];
        #pragma unroll
        for (int r = 0; r < 8; ++r)
            #pragma unroll
            for (int c = 0; c < 4; ++c) acc[r][c] = 0ull;

        #pragma unroll 8
        for (int e2 = 0; e2 < 64; ++e2) {
            ull wv[4];
            #pragma unroll
            for (int c = 0; c < 4; ++c)
                wv[c] = *(const ull*)&Ws[(tx + 32 * c) * SP + 2 * e2];
            #pragma unroll
            for (int r = 0; r < 8; ++r) {
                const ull xv = *(const ull*)&xs[(ty * 8 + r) * SP + 2 * e2];
                #pragma unroll
                for (int c = 0; c < 4; ++c) acc[r][c] = ffma2(xv, wv[c], acc[r][c]);
            }
        }

        float* O = Ol[m];
        #pragma unroll
        for (int c = 0; c < 4; ++c) {
            const float bb = bl[m][tx + 32 * c];
            #pragma unroll
            for (int r = 0; r < 8; ++r) {
                const float2 f = upk2(acc[r][c]);
                O[(size_t)(r0 + ty * 8 + r) * En + tx + 32 * c] = f.x + f.y + bb;
            }
        }
    }
}

// =====================================================================
// Kernel 2: masked attention. block = (batch b, 64-query tile)
// smem: Qs[64][SP] + KVs[64][SP] + L[64][512] + deg[64] + isum[64]
// =====================================================================
#define ATTN_SMEM_BYTES ((64 * SP * 2 + 64 * 512 + 128) * 4)

__device__ __forceinline__ void load_tile64(float* dst, const float* __restrict__ src) {
    for (int i = threadIdx.x; i < 64 * 32; i += 256) {
        float4 t = ((const float4*)src)[i];
        const int r = i >> 5, e = (i & 31) << 2;
        float* d = &dst[r * SP + e];
        d[0] = t.x; d[1] = t.y; d[2] = t.z; d[3] = t.w;
    }
}

__global__ __launch_bounds__(256) void attn_kernel(const float* __restrict__ adj)
{
    extern __shared__ float sm[];
    float* Qs   = sm;                    // 64*SP
    float* KVs  = Qs + 64 * SP;          // 64*SP
    float* L    = KVs + 64 * SP;         // 64*512
    float* deg  = L + 64 * 512;          // 64
    float* isum = deg + 64;              // 64

    const int b   = blockIdx.y;
    const int q0  = blockIdx.x * 64;
    const int tid = threadIdx.x;

    if (tid < 64) deg[tid] = 0.0f;
    load_tile64(Qs, g_q + ((size_t)b * Sn + q0) * En);
    __syncthreads();

    const int tx = tid & 15;   // key lane
    const int ty = tid >> 4;   // query lane (16)

    float degacc[4] = {0.f, 0.f, 0.f, 0.f};

    // ---- pass 1: logits = mask(Q K^T), fused adj read + degree ----
    for (int kt = 0; kt < 8; ++kt) {
        load_tile64(KVs, g_k + ((size_t)b * Sn + kt * 64) * En);
        __syncthreads();

        ull acc[4][4];
        #pragma unroll
        for (int qi = 0; qi < 4; ++qi)
            #pragma unroll
            for (int ki = 0; ki < 4; ++ki) acc[qi][ki] = 0ull;

        #pragma unroll 8
        for (int e2 = 0; e2 < 64; ++e2) {
            ull kvv[4], qvv[4];
            #pragma unroll
            for (int ki = 0; ki < 4; ++ki)
                kvv[ki] = *(const ull*)&KVs[(tx + 16 * ki) * SP + 2 * e2];
            #pragma unroll
            for (int qi = 0; qi < 4; ++qi)
                qvv[qi] = *(const ull*)&Qs[(ty + 16 * qi) * SP + 2 * e2];
            #pragma unroll
            for (int qi = 0; qi < 4; ++qi)
                #pragma unroll
                for (int ki = 0; ki < 4; ++ki)
                    acc[qi][ki] = ffma2(qvv[qi], kvv[ki], acc[qi][ki]);
        }

        #pragma unroll
        for (int qi = 0; qi < 4; ++qi) {
            const int q = ty + 16 * qi;
            const float* arow = adj + ((size_t)b * Sn + q0 + q) * Sn + kt * 64;
            #pragma unroll
            for (int ki = 0; ki < 4; ++ki) {
                const int k = tx + 16 * ki;
                const float a = arow[k];
                degacc[qi] += a;
                const float2 f = upk2(acc[qi][ki]);
                L[q * 512 + kt * 64 + k] = (a != 0.0f) ? (f.x + f.y) : -INFINITY;
            }
        }
        __syncthreads();
    }

    #pragma unroll
    for (int qi = 0; qi < 4; ++qi) atomicAdd(&deg[ty + 16 * qi], degacc[qi]);
    __syncthreads();

    // ---- softmax over 512 keys; warp handles 8 queries ----
    {
        const int w = tid >> 5, lane = tid & 31;
        for (int j = 0; j < 8; ++j) {
            const int q = w * 8 + j;
            const float s = rsqrtf(deg[q]);
            float m = -INFINITY;
            for (int kk = lane; kk < 512; kk += 32)
                m = fmaxf(m, L[q * 512 + kk] * s);
            #pragma unroll
            for (int o = 16; o; o >>= 1) m = fmaxf(m, __shfl_xor_sync(0xffffffffu, m, o));
            float sum = 0.0f;
            for (int kk = lane; kk < 512; kk += 32) {
                const float p = __expf(L[q * 512 + kk] * s - m);
                L[q * 512 + kk] = p;
                sum += p;
            }
            #pragma unroll
            for (int o = 16; o; o >>= 1) sum += __shfl_xor_sync(0xffffffffu, sum, o);
            if (lane == 0) isum[q] = 1.0f / sum;
        }
    }
    __syncthreads();

    // ---- pass 2: out = P V ----
    ull oacc[4][4];   // 4 queries x 4 float2 output slots (8 cols)
    #pragma unroll
    for (int qi = 0; qi < 4; ++qi)
        #pragma unroll
        for (int ei = 0; ei < 4; ++ei) oacc[qi][ei] = 0ull;

    for (int kt = 0; kt < 8; ++kt) {
        load_tile64(KVs, g_v + ((size_t)b * Sn + kt * 64) * En);
        __syncthreads();

        #pragma unroll 4
        for (int k = 0; k < 64; ++k) {
            ull vv[4];
            #pragma unroll
            for (int ei = 0; ei < 4; ++ei)
                vv[ei] = *(const ull*)&KVs[k * SP + 2 * (tx + 16 * ei)];
            #pragma unroll
            for (int qi = 0; qi < 4; ++qi) {
                const float p = L[(ty + 16 * qi) * 512 + kt * 64 + k];
                const ull p2 = pk2(p, p);
                #pragma unroll
                for (int ei = 0; ei < 4; ++ei)
                    oacc[qi][ei] = ffma2(p2, vv[ei], oacc[qi][ei]);
            }
        }
        __syncthreads();
    }

    float* Og = g_ao + ((size_t)b * Sn + q0) * En;
    #pragma unroll
    for (int qi = 0; qi < 4; ++qi) {
        const int q = ty + 16 * qi;
        const float is = isum[q];
        #pragma unroll
        for (int ei = 0; ei < 4; ++ei) {
            const float2 f = upk2(oacc[qi][ei]);
            *(float2*)&Og[q * En + 2 * (tx + 16 * ei)] = make_float2(f.x * is, f.y * is);
        }
    }
}

// =====================================================================
// Kernel 3: LN + ReLU + output projection + residual
// =====================================================================
__global__ __launch_bounds__(256, 2) void out_kernel(
    const float* __restrict__ x,
    const float* __restrict__ Wo, const float* __restrict__ bo,
    float* __restrict__ out)
{
    extern __shared__ float sm[];
    float* xs = sm;
    float* Ws = sm + 64 * SP;

    const int tid  = threadIdx.x;
    const int r0   = blockIdx.x * 64;
    const int w    = tid >> 5;
    const int lane = tid & 31;

    #pragma unroll
    for (int r = 0; r < 8; ++r) {
        const int row = w * 8 + r;
        float4 v = ((const float4*)(g_ao + (size_t)(r0 + row) * En))[lane];
        float s = v.x + v.y + v.z + v.w;
        #pragma unroll
        for (int o = 16; o; o >>= 1) s += __shfl_xor_sync(0xffffffffu, s, o);
        const float mean = s * (1.0f / En);
        const float a0 = v.x - mean, a1 = v.y - mean, a2 = v.z - mean, a3 = v.w - mean;
        float q = a0 * a0 + a1 * a1 + a2 * a2 + a3 * a3;
        #pragma unroll
        for (int o = 16; o; o >>= 1) q += __shfl_xor_sync(0xffffffffu, q, o);
        const float rs = rsqrtf(q * (1.0f / En) + 1e-5f);
        float* d = &xs[row * SP + lane * 4];
        d[0] = fmaxf(a0 * rs, 0.0f);
        d[1] = fmaxf(a1 * rs, 0.0f);
        d[2] = fmaxf(a2 * rs, 0.0f);
        d[3] = fmaxf(a3 * rs, 0.0f);
    }
    __syncthreads();

    for (int i = tid; i < 128 * 32; i += 256) {
        float4 t = ((const float4*)Wo)[i];
        const int c = i >> 5, e = (i & 31) << 2;
        float* d = &Ws[c * SP + e];
        d[0] = t.x; d[1] = t.y; d[2] = t.z; d[3] = t.w;
    }
    __syncthreads();

    const int tx = tid & 31;
    const int ty = tid >> 5;

    ull acc[8][4];
    #pragma unroll
    for (int r = 0; r < 8; ++r)
        #pragma unroll
        for (int c = 0; c < 4; ++c) acc[r][c] = 0ull;

    #pragma unroll 8
    for (int e2 = 0; e2 < 64; ++e2) {
        ull wv[4];
        #pragma unroll
        for (int c = 0; c < 4; ++c)
            wv[c] = *(const ull*)&Ws[(tx + 32 * c) * SP + 2 * e2];
        #pragma unroll
        for (int r = 0; r < 8; ++r) {
            const ull xv = *(const ull*)&xs[(ty * 8 + r) * SP + 2 * e2];
            #pragma unroll
            for (int c = 0; c < 4; ++c) acc[r][c] = ffma2(xv, wv[c], acc[r][c]);
        }
    }

    #pragma unroll
    for (int c = 0; c < 4; ++c) {
        const float bb = bo[tx + 32 * c];
        #pragma unroll
        for (int r = 0; r < 8; ++r) {
            const size_t idx = (size_t)(r0 + ty * 8 + r) * En + tx + 32 * c;
            const float2 f = upk2(acc[r][c]);
            out[idx] = x[idx] + f.x + f.y + bb;
        }
    }
}

// =====================================================================
extern "C" void kernel_launch(void* const* d_in, const int* in_sizes, int n_in,
                              void* d_out, int out_size) {
    const float* x   = (const float*)d_in[0];
    const float* adj = (const float*)d_in[1];
    const float* Wq  = (const float*)d_in[2];
    const float* bq  = (const float*)d_in[3];
    const float* Wk  = (const float*)d_in[4];
    const float* bk  = (const float*)d_in[5];
    const float* Wv  = (const float*)d_in[6];
    const float* bv  = (const float*)d_in[7];
    const float* Wo  = (const float*)d_in[8];
    const float* bo  = (const float*)d_in[9];
    float* out = (float*)d_out;

    cudaFuncSetAttribute(qkv_kernel,  cudaFuncAttributeMaxDynamicSharedMemorySize, QKV_SMEM_BYTES);
    cudaFuncSetAttribute(attn_kernel, cudaFuncAttributeMaxDynamicSharedMemorySize, ATTN_SMEM_BYTES);
    cudaFuncSetAttribute(out_kernel,  cudaFuncAttributeMaxDynamicSharedMemorySize, QKV_SMEM_BYTES);

    qkv_kernel<<<Nrows / 64, 256, QKV_SMEM_BYTES>>>(x, Wq, bq, Wk, bk, Wv, bv);
    attn_kernel<<<dim3(Sn / 64, Bn), 256, ATTN_SMEM_BYTES>>>(adj);
    out_kernel<<<Nrows / 64, 256, QKV_SMEM_BYTES>>>(x, Wo, bo, out);
}